// round 5
// baseline (speedup 1.0000x reference)
#include <cuda_runtime.h>
#include <math.h>

// Shapes
#define V_SZ 50257
#define E_SZ 512
#define H_SZ 1024
#define C_SZ 1024
#define S_SZ 2048
#define NRC 8               // row-chunks for wsum partials

// ---------------- scratch (device globals) --------------------------------------
__device__ __align__(16) float g_q[H_SZ];               // rnn_output
__device__ __align__(16) float g_u[3][C_SZ];            // W^T q per head
__device__            float g_bq[3];                    // b . q per head
__device__ __align__(16) float g_e[3][S_SZ];            // attention logits
__device__ __align__(16) float g_wpart[3][NRC][C_SZ];   // wsum row-chunk partials
__device__ __align__(16) float g_concat_out[H_SZ];

// ---------------- helpers --------------------------------------------------------
__device__ __forceinline__ float warp_sum(float v) {
#pragma unroll
    for (int o = 16; o; o >>= 1) v += __shfl_xor_sync(0xffffffffu, v, o);
    return v;
}
__device__ __forceinline__ float warp_max(float v) {
#pragma unroll
    for (int o = 16; o; o >>= 1) v = fmaxf(v, __shfl_xor_sync(0xffffffffu, v, o));
    return v;
}
__device__ __forceinline__ float sigf(float x) { return 1.0f / (1.0f + expf(-x)); }
__device__ __forceinline__ float dot4(float4 w, float4 v) {
    return w.x * v.x + w.y * v.y + w.z * v.z + w.w * v.w;
}

// ---------------- K1/K2: LSTM gates + fused activation ---------------------------
// block 256 (8 warps): warp w -> gate gi=w>>1, jj=w&1; j = blk*2+jj. grid 512.
// PDL: entire weight row (Wih + Whh) prefetched into regs BEFORE griddepsync.
__global__ void k_gates(const float* __restrict__ Wih, int lenA,
                        const float* __restrict__ Whh,
                        const float* __restrict__ bih, const float* __restrict__ bhh,
                        const float* __restrict__ xbase, const int* __restrict__ idx,
                        const float* __restrict__ hprev,
                        const float* __restrict__ cprev,
                        float* __restrict__ hout, float* __restrict__ cout,
                        int copy_q) {
    cudaTriggerProgrammaticLaunchCompletion();
    extern __shared__ float sh[];            // lenA + H + 8
    float* gate_sm = sh + lenA + H_SZ;       // [4][2]
    const int tid  = threadIdx.x;
    const int w    = tid >> 5;
    const int lane = tid & 31;
    const int gi   = w >> 1;
    const int jj   = w & 1;
    const int j    = blockIdx.x * 2 + jj;
    const int row  = gi * H_SZ + j;
    const int nA   = lenA >> 2;              // 128 or 256
    const int nH   = H_SZ >> 2;              // 256

    // ---- prefetch full weight row (independent of predecessor) ----
    const float4* a = (const float4*)(Wih + (size_t)row * lenA);
    const float4* b = (const float4*)(Whh + (size_t)row * H_SZ);
    float4 wvA[8], wvB[8];
#pragma unroll
    for (int k = 0; k < 8; k++) {
        int i = lane + 32 * k;
        if (i < nA) wvA[k] = a[i];
    }
#pragma unroll
    for (int k = 0; k < 8; k++) wvB[k] = b[lane + 32 * k];

    cudaGridDependencySynchronize();

    // ---- stage x and hprev ----
    const float* x = idx ? (xbase + (size_t)idx[0] * lenA) : xbase;
    for (int i = tid; i < lenA; i += 256) sh[i] = x[i];
    for (int i = tid; i < H_SZ; i += 256) sh[lenA + i] = hprev[i];
    __syncthreads();

    const float4* x4 = (const float4*)sh;
    const float4* h4 = (const float4*)(sh + lenA);
    float s = 0.f;
#pragma unroll
    for (int k = 0; k < 8; k++) {
        int i = lane + 32 * k;
        if (i < nA) s += dot4(wvA[k], x4[i]);
    }
#pragma unroll
    for (int k = 0; k < 8; k++) s += dot4(wvB[k], h4[lane + 32 * k]);
    s = warp_sum(s);
    if (lane == 0) gate_sm[gi * 2 + jj] = s + bih[row] + bhh[row];
    __syncthreads();

    if (tid < 2) {
        const int jo = blockIdx.x * 2 + tid;
        const float ig = sigf (gate_sm[tid]);
        const float fg = sigf (gate_sm[2 + tid]);
        const float gg = tanhf(gate_sm[4 + tid]);
        const float og = sigf (gate_sm[6 + tid]);
        const float c = fg * cprev[jo] + ig * gg;
        const float h = og * tanhf(c);
        cout[jo] = c;
        hout[jo] = h;
        if (copy_q) g_q[jo] = h;
    }
}

// ---------------- K3: u = W^T q (+ bq in chunk 0) --------------------------------
// grid dim3(64, 3). block 256. Thread: f4-col = t&3, rowgroup = t>>2; 16 rows.
// PDL: all 16 weight loads issued before griddepsync.
__global__ void k_u(const float* __restrict__ WL,
                    const float* __restrict__ WR,
                    const float* __restrict__ WM,
                    const float* __restrict__ bL,
                    const float* __restrict__ bR,
                    const float* __restrict__ bM) {
    cudaTriggerProgrammaticLaunchCompletion();
    __shared__ float  shq[H_SZ];
    __shared__ float4 red[64][4];
    __shared__ float  redb[8];
    const int hd = blockIdx.y;
    const float* W    = (hd == 0) ? WL : (hd == 1) ? WR : WM;
    const float* bias = (hd == 0) ? bL : (hd == 1) ? bR : bM;
    const int tid  = threadIdx.x;
    const int col  = tid & 3;
    const int rgrp = tid >> 2;                 // 0..63
    const int c4   = blockIdx.x * 4 + col;     // f4 column (0..255)
    const float4* W4 = (const float4*)W;

    float4 wv[16];
#pragma unroll
    for (int k = 0; k < 16; k++)
        wv[k] = W4[(size_t)(rgrp + 64 * k) * (C_SZ >> 2) + c4];

    cudaGridDependencySynchronize();
    for (int i = tid; i < H_SZ; i += 256) shq[i] = g_q[i];
    __syncthreads();

    float4 acc = make_float4(0.f, 0.f, 0.f, 0.f);
#pragma unroll
    for (int k = 0; k < 16; k++) {
        float qv = shq[rgrp + 64 * k];
        acc.x += wv[k].x * qv; acc.y += wv[k].y * qv;
        acc.z += wv[k].z * qv; acc.w += wv[k].w * qv;
    }
    red[rgrp][col] = acc;
    __syncthreads();
#pragma unroll
    for (int sdist = 32; sdist >= 1; sdist >>= 1) {
        if (rgrp < sdist) {
            float4 o = red[rgrp + sdist][col];
            float4 m = red[rgrp][col];
            m.x += o.x; m.y += o.y; m.z += o.z; m.w += o.w;
            red[rgrp][col] = m;
        }
        __syncthreads();
    }
    if (tid < 4) ((float4*)g_u[hd])[blockIdx.x * 4 + tid] = red[0][tid];

    if (blockIdx.x == 0) {      // bq = bias . q, deterministic fixed-order
        float v = 0.f;
#pragma unroll
        for (int i = tid; i < H_SZ; i += 256) v += bias[i] * shq[i];
        v = warp_sum(v);
        if ((tid & 31) == 0) redb[tid >> 5] = v;
        __syncthreads();
        if (tid < 32) {
            float t = (tid < 8) ? redb[tid] : 0.f;
            t = warp_sum(t);
            if (tid == 0) g_bq[hd] = t;
        }
    }
}

// ---------------- K4: e[hd][s] = ctx[s,:]·u[hd] + bq[hd] -------------------------
// warp-per-row, 8 warps/block, grid 768. PDL: full ctx row prefetched pre-sync.
__global__ void k_e(const float* __restrict__ ctxL,
                    const float* __restrict__ ctxR,
                    const float* __restrict__ ctxM) {
    cudaTriggerProgrammaticLaunchCompletion();
    __shared__ float su[C_SZ];
    const int tid  = threadIdx.x;
    const int row  = blockIdx.x * 8 + (tid >> 5);
    const int hd   = row >> 11;
    const int srow = row & (S_SZ - 1);
    const int lane = tid & 31;

    const float* ctx = (hd == 0) ? ctxL : (hd == 1) ? ctxR : ctxM;
    const float4* c4 = (const float4*)(ctx + (size_t)srow * C_SZ);
    float4 wv[8];
#pragma unroll
    for (int k = 0; k < 8; k++) wv[k] = c4[lane + 32 * k];   // 256 f4 per row

    cudaGridDependencySynchronize();
    for (int i = tid; i < C_SZ; i += 256) su[i] = g_u[hd][i];
    __syncthreads();

    const float4* u4 = (const float4*)su;
    float s = 0.f;
#pragma unroll
    for (int k = 0; k < 8; k++) s += dot4(wv[k], u4[lane + 32 * k]);
    s = warp_sum(s);
    if (lane == 0) g_e[hd][srow] = s + g_bq[hd];
}

// ---------------- K5: fused softmax + weighted column-sum partials ---------------
// grid dim3(8, NRC, 3) = 192 blocks, block 256. First row batch prefetched.
__global__ void k_wsum(const float* __restrict__ ctxL,
                       const float* __restrict__ ctxR,
                       const float* __restrict__ ctxM) {
    cudaTriggerProgrammaticLaunchCompletion();
    __shared__ float  sha[S_SZ / NRC];     // 256 weights
    __shared__ float  red[8];
    __shared__ float4 red4[8][32];
    __shared__ float  sM, sZ;
    const int hd  = blockIdx.z;
    const int s0  = blockIdx.y * (S_SZ / NRC);
    const int tid = threadIdx.x;
    const int lane = tid & 31, grp = tid >> 5;

    const float* ctx = (hd == 0) ? ctxL : (hd == 1) ? ctxR : ctxM;
    const float4* c4p = (const float4*)ctx;
    const int c4 = blockIdx.x * 32 + lane;

    // prefetch batch 0 (rows s0+grp+8k) — independent of predecessor
    float4 v0[8];
#pragma unroll
    for (int k = 0; k < 8; k++)
        v0[k] = c4p[(size_t)(s0 + grp + 8 * k) * (C_SZ >> 2) + c4];

    cudaGridDependencySynchronize();

    // softmax stats over full 2048 logits (deterministic fixed order)
    float le[8], lmax = -1e30f;
#pragma unroll
    for (int k = 0; k < 8; k++) {
        le[k] = g_e[hd][tid + k * 256];
        lmax = fmaxf(lmax, le[k]);
    }
    lmax = warp_max(lmax);
    if (lane == 0) red[grp] = lmax;
    __syncthreads();
    if (tid < 32) {
        float v = (tid < 8) ? red[tid] : -1e30f;
        v = warp_max(v);
        if (tid == 0) sM = v;
    }
    __syncthreads();
    const float M = sM;
    float lsum = 0.f;
#pragma unroll
    for (int k = 0; k < 8; k++) lsum += expf(le[k] - M);
    lsum = warp_sum(lsum);
    __syncthreads();
    if (lane == 0) red[grp] = lsum;
    __syncthreads();
    if (tid < 32) {
        float v = (tid < 8) ? red[tid] : 0.f;
        v = warp_sum(v);
        if (tid == 0) sZ = v;
    }
    __syncthreads();
    const float inv = 1.0f / sZ;
    if (tid < S_SZ / NRC) sha[tid] = expf(g_e[hd][s0 + tid] - M) * inv;
    __syncthreads();

    // weighted column sum: batch 0 from prefetch, batches 1..3 streamed (L2 hits)
    float4 acc = make_float4(0.f, 0.f, 0.f, 0.f);
#pragma unroll
    for (int k = 0; k < 8; k++) {
        float av = sha[grp + 8 * k];
        acc.x += v0[k].x * av; acc.y += v0[k].y * av;
        acc.z += v0[k].z * av; acc.w += v0[k].w * av;
    }
    for (int sb = 64; sb < S_SZ / NRC; sb += 64) {
        float4 v[8];
#pragma unroll
        for (int k = 0; k < 8; k++)
            v[k] = c4p[(size_t)(s0 + sb + grp + 8 * k) * (C_SZ >> 2) + c4];
#pragma unroll
        for (int k = 0; k < 8; k++) {
            float av = sha[sb + grp + 8 * k];
            acc.x += v[k].x * av; acc.y += v[k].y * av;
            acc.z += v[k].z * av; acc.w += v[k].w * av;
        }
    }
    red4[grp][lane] = acc;
    __syncthreads();
    if (grp == 0) {
        float4 t = red4[0][lane];
#pragma unroll
        for (int k = 1; k < 8; k++) {
            float4 p = red4[k][lane];
            t.x += p.x; t.y += p.y; t.z += p.z; t.w += p.w;
        }
        ((float4*)g_wpart[hd][blockIdx.y])[blockIdx.x * 32 + lane] = t;
    }
}

// ---------------- K6: concat_out = tanh(W_concat @ [q|l|r|m] + b) ----------------
// grid 128, block 256. Batch 0 of weights prefetched pre-sync.
__global__ void k_concat_gemv(const float* __restrict__ Wc,
                              const float* __restrict__ bc) {
    cudaTriggerProgrammaticLaunchCompletion();
    __shared__ float shx[4 * H_SZ];
    const int tid  = threadIdx.x;
    const int row  = blockIdx.x * 8 + (tid >> 5);
    const int lane = tid & 31;
    const float4* a = (const float4*)(Wc + (size_t)row * 4 * H_SZ);

    float4 wv0[8];
#pragma unroll
    for (int k = 0; k < 8; k++) wv0[k] = a[lane + 32 * k];

    cudaGridDependencySynchronize();
    for (int i = tid; i < 4 * H_SZ; i += 256) {
        float v;
        if (i < H_SZ) v = g_q[i];
        else {
            const int hd = (i >> 10) - 1;
            const int c = i & (H_SZ - 1);
            float s = 0.f;
#pragma unroll
            for (int k = 0; k < NRC; k++) s += g_wpart[hd][k][c];
            v = s;
        }
        shx[i] = v;
    }
    __syncthreads();

    const float4* x4 = (const float4*)shx;
    float s = 0.f;
#pragma unroll
    for (int k = 0; k < 8; k++) s += dot4(wv0[k], x4[lane + 32 * k]);
    for (int i0 = 256; i0 < H_SZ; i0 += 256) {   // remaining 3 batches
        float4 wv[8];
#pragma unroll
        for (int k = 0; k < 8; k++) wv[k] = a[i0 + lane + 32 * k];
#pragma unroll
        for (int k = 0; k < 8; k++) s += dot4(wv[k], x4[i0 + lane + 32 * k]);
    }
    s = warp_sum(s);
    if (lane == 0) g_concat_out[row] = tanhf(s + bc[row]);
}

// ---------------- K7: output = W_out @ concat_out + b_out ------------------------
// warp-per-row, grid 6283, block 256. Full Wo row prefetched pre-sync so the
// 206 MB stream overlaps k_concat via PDL.
__global__ void k_out_gemv(const float* __restrict__ Wo,
                           const float* __restrict__ bo,
                           float* __restrict__ out) {
    cudaTriggerProgrammaticLaunchCompletion();
    __shared__ float shx[H_SZ];
    const int tid  = threadIdx.x;
    const int row  = blockIdx.x * 8 + (tid >> 5);
    const int lane = tid & 31;
    const bool valid = row < V_SZ;

    float4 wv[8];
    if (valid) {
        const float4* a = (const float4*)(Wo + (size_t)row * H_SZ);
#pragma unroll
        for (int k = 0; k < 8; k++) wv[k] = a[lane + 32 * k];   // 256 f4 per row
    }

    cudaGridDependencySynchronize();
    for (int i = tid; i < H_SZ; i += 256) shx[i] = g_concat_out[i];
    __syncthreads();
    if (!valid) return;

    const float4* x4 = (const float4*)shx;
    float s = 0.f;
#pragma unroll
    for (int k = 0; k < 8; k++) s += dot4(wv[k], x4[lane + 32 * k]);
    s = warp_sum(s);
    if (lane == 0) out[row] = s + bo[row];
}

// ==================================================================================
template <typename F>
static void launch_pdl_raw(F kern, dim3 grid, dim3 block, size_t smem,
                           void** args) {
    cudaLaunchConfig_t cfg = {};
    cfg.gridDim = grid;
    cfg.blockDim = block;
    cfg.dynamicSmemBytes = smem;
    cfg.stream = 0;
    cudaLaunchAttribute attr[1];
    attr[0].id = cudaLaunchAttributeProgrammaticStreamSerialization;
    attr[0].val.programmaticStreamSerializationAllowed = 1;
    cfg.attrs = attr;
    cfg.numAttrs = 1;
    cudaLaunchKernelExC(&cfg, (const void*)kern, args);
}

extern "C" void kernel_launch(void* const* d_in, const int* in_sizes, int n_in,
                              void* d_out, int out_size) {
    const int*   input_ids = (const int*)  d_in[0];
    const float* h0        = (const float*)d_in[1];
    const float* c0        = (const float*)d_in[2];
    const float* ctxL      = (const float*)d_in[3];
    const float* ctxR      = (const float*)d_in[4];
    const float* ctxM      = (const float*)d_in[5];
    const float* emb       = (const float*)d_in[6];
    const float* Wih0      = (const float*)d_in[7];
    const float* Whh0      = (const float*)d_in[8];
    const float* bih0      = (const float*)d_in[9];
    const float* bhh0      = (const float*)d_in[10];
    const float* Wih1      = (const float*)d_in[11];
    const float* Whh1      = (const float*)d_in[12];
    const float* bih1      = (const float*)d_in[13];
    const float* bhh1      = (const float*)d_in[14];
    const float* WL        = (const float*)d_in[15];
    const float* bL        = (const float*)d_in[16];
    const float* WR        = (const float*)d_in[17];
    const float* bR        = (const float*)d_in[18];
    const float* WM        = (const float*)d_in[19];
    const float* bM        = (const float*)d_in[20];
    const float* Wc        = (const float*)d_in[21];
    const float* bc        = (const float*)d_in[22];
    const float* Wo        = (const float*)d_in[23];
    const float* bo        = (const float*)d_in[24];

    float* out   = (float*)d_out;            // [V]
    float* h_new = out + V_SZ;               // [2*H]
    float* c_new = out + V_SZ + 2 * H_SZ;    // [2*H]

    const size_t sm0 = (E_SZ + H_SZ + 8) * sizeof(float);
    const size_t sm1 = (H_SZ + H_SZ + 8) * sizeof(float);

    // ---- LSTM layer 0 (x = embedding[input_ids]) ----
    {
        int lenA = E_SZ, copyq = 0;
        const float* xb = emb;       const int* ix = input_ids;
        const float* hp = h0;        const float* cp = c0;
        float* ho = h_new;           float* co = c_new;
        void* args[] = { &Wih0, &lenA, &Whh0, &bih0, &bhh0, &xb, &ix,
                         &hp, &cp, &ho, &co, &copyq };
        launch_pdl_raw(k_gates, dim3(512), dim3(256), sm0, args);
    }
    // ---- LSTM layer 1 (x = h_0), writes q ----
    {
        int lenA = H_SZ, copyq = 1;
        const float* xb = h_new;     const int* ix = nullptr;
        const float* hp = h0 + H_SZ; const float* cp = c0 + H_SZ;
        float* ho = h_new + H_SZ;    float* co = c_new + H_SZ;
        void* args[] = { &Wih1, &lenA, &Whh1, &bih1, &bhh1, &xb, &ix,
                         &hp, &cp, &ho, &co, &copyq };
        launch_pdl_raw(k_gates, dim3(512), dim3(256), sm1, args);
    }
    // ---- u = W^T q and bq = b.q (3 heads) ----
    {
        void* args[] = { &WL, &WR, &WM, &bL, &bR, &bM };
        launch_pdl_raw(k_u, dim3(64, 3), dim3(256), 0, args);
    }
    // ---- e = ctx.u + bq ----
    {
        void* args[] = { &ctxL, &ctxR, &ctxM };
        launch_pdl_raw(k_e, dim3(768), dim3(256), 0, args);
    }
    // ---- fused softmax + weighted column sums (partials) ----
    {
        void* args[] = { &ctxL, &ctxR, &ctxM };
        launch_pdl_raw(k_wsum, dim3(8, NRC, 3), dim3(256), 0, args);
    }
    // ---- concat GEMV (+ partial reduce) with tanh ----
    {
        void* args[] = { &Wc, &bc };
        launch_pdl_raw(k_concat_gemv, dim3(128), dim3(256), 0, args);
    }
    // ---- vocab GEMV ----
    {
        void* args[] = { &Wo, &bo, &out };
        launch_pdl_raw(k_out_gemv, dim3((V_SZ + 7) / 8), dim3(256), 0, args);
    }
}

// round 6
// speedup vs baseline: 1.1246x; 1.1246x over previous
#include <cuda_runtime.h>
#include <math.h>

// Shapes
#define V_SZ 50257
#define E_SZ 512
#define H_SZ 1024
#define C_SZ 1024
#define S_SZ 2048
#define NRC 8                // row-chunks for wsum partials
#define NBLK 148             // persistent blocks (<= SM count, 1 per SM)
#define TPB 1024

// ---------------- scratch (device globals) --------------------------------------
__device__ __align__(16) float g_x[H_SZ];               // h of layer 0 (input to layer 1)
__device__ __align__(16) float g_q[H_SZ];               // rnn_output
__device__ __align__(16) float g_u[3][C_SZ];            // W^T q per head
__device__            float g_bq[3];                    // b . q per head
__device__ __align__(16) float g_e[3][S_SZ];            // attention logits
__device__ __align__(16) float g_wpart[3][NRC][C_SZ];   // wsum row-chunk partials
__device__ __align__(16) float g_co[H_SZ];              // concat_out

// ---------------- device-wide barrier (sense-reversal, replay-safe) --------------
__device__ unsigned g_barc;                 // arrival counter (reset each use)
__device__ volatile unsigned g_barg;        // generation (monotonic across replays)

__device__ __forceinline__ void gbar() {
    __syncthreads();
    if (threadIdx.x == 0) {
        __threadfence();                    // publish this block's writes
        unsigned gen = g_barg;
        if (atomicAdd(&g_barc, 1u) == NBLK - 1) {
            atomicExch(&g_barc, 0u);        // reset BEFORE releasing
            __threadfence();
            g_barg = gen + 1;               // release
        } else {
            while (g_barg == gen) { __nanosleep(64); }
        }
        __threadfence();                    // acquire
    }
    __syncthreads();
}

// ---------------- helpers --------------------------------------------------------
__device__ __forceinline__ float warp_sum(float v) {
#pragma unroll
    for (int o = 16; o; o >>= 1) v += __shfl_xor_sync(0xffffffffu, v, o);
    return v;
}
__device__ __forceinline__ float warp_max(float v) {
#pragma unroll
    for (int o = 16; o; o >>= 1) v = fmaxf(v, __shfl_xor_sync(0xffffffffu, v, o));
    return v;
}
__device__ __forceinline__ float sigf(float x) { return 1.0f / (1.0f + expf(-x)); }
__device__ __forceinline__ float dot4(float4 w, float4 v) {
    return w.x * v.x + w.y * v.y + w.z * v.z + w.w * v.w;
}

// ==================================================================================
__global__ __launch_bounds__(TPB, 1) void megakernel(
    const int* __restrict__ idx,
    const float* __restrict__ h0,  const float* __restrict__ c0,
    const float* __restrict__ ctxL, const float* __restrict__ ctxR,
    const float* __restrict__ ctxM, const float* __restrict__ emb,
    const float* __restrict__ Wih0, const float* __restrict__ Whh0,
    const float* __restrict__ bih0, const float* __restrict__ bhh0,
    const float* __restrict__ Wih1, const float* __restrict__ Whh1,
    const float* __restrict__ bih1, const float* __restrict__ bhh1,
    const float* __restrict__ WL, const float* __restrict__ bL,
    const float* __restrict__ WR, const float* __restrict__ bR,
    const float* __restrict__ WM, const float* __restrict__ bM,
    const float* __restrict__ Wc, const float* __restrict__ bc,
    const float* __restrict__ Wo, const float* __restrict__ bo,
    float* __restrict__ out, float* __restrict__ h_new, float* __restrict__ c_new)
{
    __shared__ __align__(16) float sm[5200];
    const int tid  = threadIdx.x;
    const int wid  = tid >> 5;
    const int lane = tid & 31;
    const int bid  = blockIdx.x;
    const int gw   = bid * 32 + wid;

    // ============ P1: LSTM layer 0 gates + activation (blocks 0..127) ============
    if (bid < 128) {
        const float* x = emb + (size_t)idx[0] * E_SZ;
        for (int i = tid; i < E_SZ; i += TPB) sm[i] = x[i];
        for (int i = tid; i < H_SZ; i += TPB) sm[E_SZ + i] = h0[i];
        __syncthreads();

        const int gi = wid >> 3, jj = wid & 7;
        const int j = bid * 8 + jj;
        const int row = gi * H_SZ + j;
        const float4* a  = (const float4*)(Wih0 + (size_t)row * E_SZ);
        const float4* b  = (const float4*)(Whh0 + (size_t)row * H_SZ);
        const float4* x4 = (const float4*)sm;
        const float4* h4 = (const float4*)(sm + E_SZ);

        float s = 0.f;
        {   // x part: 128 f4, 4 per lane
            float4 wv[4];
#pragma unroll
            for (int k = 0; k < 4; k++) wv[k] = a[lane + 32 * k];
#pragma unroll
            for (int k = 0; k < 4; k++) s += dot4(wv[k], x4[lane + 32 * k]);
        }
        {   // h part: 256 f4, 8 per lane
            float4 wv[8];
#pragma unroll
            for (int k = 0; k < 8; k++) wv[k] = b[lane + 32 * k];
#pragma unroll
            for (int k = 0; k < 8; k++) s += dot4(wv[k], h4[lane + 32 * k]);
        }
        s = warp_sum(s);
        if (lane == 0) sm[1536 + gi * 8 + jj] = s + bih0[row] + bhh0[row];
        __syncthreads();

        if (tid < 8) {
            const int jo = bid * 8 + tid;
            const float ig = sigf (sm[1536 + tid]);
            const float fg = sigf (sm[1536 + 8 + tid]);
            const float gg = tanhf(sm[1536 + 16 + tid]);
            const float og = sigf (sm[1536 + 24 + tid]);
            const float c = fg * c0[jo] + ig * gg;
            const float h = og * tanhf(c);
            c_new[jo] = c;
            h_new[jo] = h;
            g_x[jo]  = h;
        }
    }
    gbar();

    // ============ P2: LSTM layer 1 gates + activation, writes q ==================
    if (bid < 128) {
        for (int i = tid; i < H_SZ; i += TPB) sm[i] = g_x[i];
        for (int i = tid; i < H_SZ; i += TPB) sm[H_SZ + i] = h0[H_SZ + i];
        __syncthreads();

        const int gi = wid >> 3, jj = wid & 7;
        const int j = bid * 8 + jj;
        const int row = gi * H_SZ + j;
        const float4* a  = (const float4*)(Wih1 + (size_t)row * H_SZ);
        const float4* b  = (const float4*)(Whh1 + (size_t)row * H_SZ);
        const float4* x4 = (const float4*)sm;
        const float4* h4 = (const float4*)(sm + H_SZ);

        float s = 0.f;
        {
            float4 wv[8];
#pragma unroll
            for (int k = 0; k < 8; k++) wv[k] = a[lane + 32 * k];
#pragma unroll
            for (int k = 0; k < 8; k++) s += dot4(wv[k], x4[lane + 32 * k]);
        }
        {
            float4 wv[8];
#pragma unroll
            for (int k = 0; k < 8; k++) wv[k] = b[lane + 32 * k];
#pragma unroll
            for (int k = 0; k < 8; k++) s += dot4(wv[k], h4[lane + 32 * k]);
        }
        s = warp_sum(s);
        if (lane == 0) sm[2048 + gi * 8 + jj] = s + bih1[row] + bhh1[row];
        __syncthreads();

        if (tid < 8) {
            const int jo = bid * 8 + tid;
            const float ig = sigf (sm[2048 + tid]);
            const float fg = sigf (sm[2048 + 8 + tid]);
            const float gg = tanhf(sm[2048 + 16 + tid]);
            const float og = sigf (sm[2048 + 24 + tid]);
            const float c = fg * c0[H_SZ + jo] + ig * gg;
            const float h = og * tanhf(c);
            c_new[H_SZ + jo] = c;
            h_new[H_SZ + jo] = h;
            g_q[jo] = h;
        }
    }
    gbar();

    // ============ P3: u = W^T q (+ bq) — 192 virtual blocks ======================
    for (int i = tid; i < H_SZ; i += TPB) sm[i] = g_q[i];
    __syncthreads();
    for (int vb = bid; vb < 192; vb += NBLK) {
        const int hd = vb >> 6, chunk = vb & 63;
        const float* W    = (hd == 0) ? WL : (hd == 1) ? WR : WM;
        const float* bias = (hd == 0) ? bL : (hd == 1) ? bR : bM;
        const int col = tid & 3, rgrp = tid >> 2;        // 4 f4 cols, 256 rowgroups
        const int c4 = chunk * 4 + col;
        const float4* W4 = (const float4*)W;

        float4 wv[4];
#pragma unroll
        for (int k = 0; k < 4; k++)
            wv[k] = W4[(size_t)(rgrp + 256 * k) * (C_SZ >> 2) + c4];
        float4 acc = make_float4(0.f, 0.f, 0.f, 0.f);
#pragma unroll
        for (int k = 0; k < 4; k++) {
            float qv = sm[rgrp + 256 * k];
            acc.x += wv[k].x * qv; acc.y += wv[k].y * qv;
            acc.z += wv[k].z * qv; acc.w += wv[k].w * qv;
        }
        float4* red = (float4*)(sm + H_SZ);              // 1024 float4
        red[rgrp * 4 + col] = acc;
        __syncthreads();
#pragma unroll
        for (int sd = 128; sd >= 1; sd >>= 1) {
            if (rgrp < sd) {
                float4 o = red[(rgrp + sd) * 4 + col];
                float4 m = red[rgrp * 4 + col];
                m.x += o.x; m.y += o.y; m.z += o.z; m.w += o.w;
                red[rgrp * 4 + col] = m;
            }
            __syncthreads();
        }
        if (tid < 4) ((float4*)g_u[hd])[chunk * 4 + tid] = red[tid];

        if (chunk == 0) {   // bq = bias . q, fixed-order
            float v = bias[tid] * sm[tid];
            v = warp_sum(v);
            if (lane == 0) sm[5120 + wid] = v;
            __syncthreads();
            if (tid < 32) {
                float t = sm[5120 + tid];
                t = warp_sum(t);
                if (tid == 0) g_bq[hd] = t;
            }
        }
        __syncthreads();
    }
    gbar();

    // ============ P4: e[hd][s] = ctx[s,:]·u[hd] + bq[hd] =========================
    for (int i = tid; i < 3 * C_SZ; i += TPB) sm[i] = ((const float*)g_u)[i];
    __syncthreads();
    for (int r = gw; r < 3 * S_SZ; r += NBLK * 32) {
        const int hd = r >> 11, srow = r & (S_SZ - 1);
        const float* ctx = (hd == 0) ? ctxL : (hd == 1) ? ctxR : ctxM;
        const float4* c4 = (const float4*)(ctx + (size_t)srow * C_SZ);
        const float4* u4 = (const float4*)(sm + hd * C_SZ);
        float4 wv[8];
#pragma unroll
        for (int k = 0; k < 8; k++) wv[k] = c4[lane + 32 * k];
        float s = 0.f;
#pragma unroll
        for (int k = 0; k < 8; k++) s += dot4(wv[k], u4[lane + 32 * k]);
        s = warp_sum(s);
        if (lane == 0) g_e[hd][srow] = s + g_bq[hd];
    }
    gbar();

    // ============ P5: softmax + weighted column-sum partials (192 vblocks) =======
    for (int vb = bid; vb < 192; vb += NBLK) {
        const int cc = vb & 7, rc = (vb >> 3) & 7, hd = vb >> 6;
        // softmax stats (deterministic)
        const float e0 = g_e[hd][tid], e1 = g_e[hd][tid + 1024];
        float m = warp_max(fmaxf(e0, e1));
        if (lane == 0) sm[4608 + wid] = m;
        __syncthreads();
        if (tid < 32) {
            float v = sm[4608 + tid];
            v = warp_max(v);
            if (tid == 0) sm[4700] = v;
        }
        __syncthreads();
        const float M = sm[4700];
        float z = expf(e0 - M) + expf(e1 - M);
        z = warp_sum(z);
        __syncthreads();
        if (lane == 0) sm[4608 + wid] = z;
        __syncthreads();
        if (tid < 32) {
            float v = sm[4608 + tid];
            v = warp_sum(v);
            if (tid == 0) sm[4701] = v;
        }
        __syncthreads();
        const float inv = 1.0f / sm[4701];
        if (tid < 256) sm[4096 + tid] = expf(g_e[hd][rc * 256 + tid] - M) * inv;
        __syncthreads();

        // weighted column sum over 256 rows (L2-warm from P4)
        const float* ctx = (hd == 0) ? ctxL : (hd == 1) ? ctxR : ctxM;
        const float4* cp = (const float4*)ctx;
        const int c4col = cc * 32 + lane;
        float4 v[8];
#pragma unroll
        for (int k = 0; k < 8; k++)
            v[k] = cp[(size_t)(rc * 256 + wid + 32 * k) * (C_SZ >> 2) + c4col];
        float4 acc = make_float4(0.f, 0.f, 0.f, 0.f);
#pragma unroll
        for (int k = 0; k < 8; k++) {
            float av = sm[4096 + wid + 32 * k];
            acc.x += v[k].x * av; acc.y += v[k].y * av;
            acc.z += v[k].z * av; acc.w += v[k].w * av;
        }
        float4* red4 = (float4*)sm;
        red4[wid * 32 + lane] = acc;
        __syncthreads();
#pragma unroll
        for (int sd = 16; sd >= 1; sd >>= 1) {
            if (wid < sd) {
                float4 o = red4[(wid + sd) * 32 + lane];
                float4 mm = red4[wid * 32 + lane];
                mm.x += o.x; mm.y += o.y; mm.z += o.z; mm.w += o.w;
                red4[wid * 32 + lane] = mm;
            }
            __syncthreads();
        }
        if (wid == 0) ((float4*)g_wpart[hd][rc])[cc * 32 + lane] = red4[lane];
        __syncthreads();
    }
    gbar();

    // ============ P6: concat_out = tanh(Wc @ [q|l|r|m] + bc) (blocks 0..127) =====
    if (bid < 128) {
        for (int i = tid; i < 4 * H_SZ; i += TPB) {
            float v;
            if (i < H_SZ) v = g_q[i];
            else {
                const int hd = (i >> 10) - 1;
                const int c = i & (H_SZ - 1);
                float s = 0.f;
#pragma unroll
                for (int k = 0; k < NRC; k++) s += g_wpart[hd][k][c];
                v = s;
            }
            sm[i] = v;
        }
        __syncthreads();

        const int row = bid * 8 + (wid >> 2);      // 8 rows/block, 4 warps/row
        const int seg = wid & 3;
        const float4* a  = (const float4*)(Wc + (size_t)row * 4 * H_SZ + seg * H_SZ);
        const float4* x4 = (const float4*)(sm + seg * H_SZ);
        float4 wv[8];
#pragma unroll
        for (int k = 0; k < 8; k++) wv[k] = a[lane + 32 * k];
        float s = 0.f;
#pragma unroll
        for (int k = 0; k < 8; k++) s += dot4(wv[k], x4[lane + 32 * k]);
        s = warp_sum(s);
        if (lane == 0) sm[4096 + (wid >> 2) * 4 + seg] = s;
        __syncthreads();
        if (tid < 8) {
            const float t = sm[4096 + tid * 4] + sm[4096 + tid * 4 + 1] +
                            sm[4096 + tid * 4 + 2] + sm[4096 + tid * 4 + 3];
            const int ro = bid * 8 + tid;
            g_co[ro] = tanhf(t + bc[ro]);
        }
    }
    gbar();

    // ============ P7: output = Wo @ concat_out + bo ===============================
    if (tid < H_SZ) sm[tid] = g_co[tid];
    __syncthreads();
    const float4* x4 = (const float4*)sm;
    for (int r = gw; r < V_SZ; r += NBLK * 32) {
        const float4* a = (const float4*)(Wo + (size_t)r * H_SZ);
        float4 wv[8];
#pragma unroll
        for (int k = 0; k < 8; k++) wv[k] = a[lane + 32 * k];
        float s = 0.f;
#pragma unroll
        for (int k = 0; k < 8; k++) s += dot4(wv[k], x4[lane + 32 * k]);
        s = warp_sum(s);
        if (lane == 0) out[r] = s + bo[r];
    }
}

// ==================================================================================
extern "C" void kernel_launch(void* const* d_in, const int* in_sizes, int n_in,
                              void* d_out, int out_size) {
    const int*   input_ids = (const int*)  d_in[0];
    const float* h0        = (const float*)d_in[1];
    const float* c0        = (const float*)d_in[2];
    const float* ctxL      = (const float*)d_in[3];
    const float* ctxR      = (const float*)d_in[4];
    const float* ctxM      = (const float*)d_in[5];
    const float* emb       = (const float*)d_in[6];
    const float* Wih0      = (const float*)d_in[7];
    const float* Whh0      = (const float*)d_in[8];
    const float* bih0      = (const float*)d_in[9];
    const float* bhh0      = (const float*)d_in[10];
    const float* Wih1      = (const float*)d_in[11];
    const float* Whh1      = (const float*)d_in[12];
    const float* bih1      = (const float*)d_in[13];
    const float* bhh1      = (const float*)d_in[14];
    const float* WL        = (const float*)d_in[15];
    const float* bL        = (const float*)d_in[16];
    const float* WR        = (const float*)d_in[17];
    const float* bR        = (const float*)d_in[18];
    const float* WM        = (const float*)d_in[19];
    const float* bM        = (const float*)d_in[20];
    const float* Wc        = (const float*)d_in[21];
    const float* bc        = (const float*)d_in[22];
    const float* Wo        = (const float*)d_in[23];
    const float* bo        = (const float*)d_in[24];

    float* out   = (float*)d_out;            // [V]
    float* h_new = out + V_SZ;               // [2*H]
    float* c_new = out + V_SZ + 2 * H_SZ;    // [2*H]

    megakernel<<<NBLK, TPB>>>(input_ids, h0, c0, ctxL, ctxR, ctxM, emb,
                              Wih0, Whh0, bih0, bhh0, Wih1, Whh1, bih1, bhh1,
                              WL, bL, WR, bR, WM, bM, Wc, bc, Wo, bo,
                              out, h_new, c_new);
}